// round 9
// baseline (speedup 1.0000x reference)
#include <cuda_runtime.h>
#include <cuda_bf16.h>

// Problem constants
#define NTOK 16384      // B*H*W
#define KC   8192
#define DD   256
#define IMG  262144     // C*H*W
#define HW   1024

#define OUT_LOSS 4194304
#define OUT_ENC  4194305

// GEMM tiling: M = codes, N = tokens
#define CTM 128
#define CTN 256
#define CK  32
#define NCH (DD / CK)   // 8

#define NGRP (KC / 8)   // 1024 8-code groups
#define EPS_WIN  1.0e-3f
#define CAP_G 16        // candidate groups per token (128 codes max)

typedef unsigned int u32;

// -------- scratch (device globals; no allocation allowed) --------
__device__ float g_cnorm[KC];
__device__ float g_xnorm[NTOK];
__device__ int   g_idx[NTOK];
__device__ float g_partial[256];
__device__ u32   g_dmin[NTOK];
__device__ int   g_ccnt[NTOK];
__device__ int   g_cand[NTOK * CAP_G];
__device__ __align__(16) __nv_bfloat16 g_xb[NTOK * DD];       // x [b][d][hw] bf16
__device__ __align__(16) __nv_bfloat16 g_cbb[KC * DD];        // [code][d] bf16
__device__ __align__(16) __nv_bfloat16 g_gmin[NGRP * NTOK];   // [group][token] 33.5MB

// -------- helpers --------
__device__ __forceinline__ u32 smem_u32(const void* p) {
    u32 a;
    asm("{ .reg .u64 t; cvta.to.shared.u64 t, %1; cvt.u32.u64 %0, t; }" : "=r"(a) : "l"(p));
    return a;
}
__device__ __forceinline__ void ldsm4(u32& r0, u32& r1, u32& r2, u32& r3, u32 a) {
    asm volatile("ldmatrix.sync.aligned.m8n8.x4.shared.b16 {%0,%1,%2,%3}, [%4];"
                 : "=r"(r0), "=r"(r1), "=r"(r2), "=r"(r3) : "r"(a));
}
__device__ __forceinline__ void ldsm4t(u32& r0, u32& r1, u32& r2, u32& r3, u32 a) {
    asm volatile("ldmatrix.sync.aligned.m8n8.x4.trans.shared.b16 {%0,%1,%2,%3}, [%4];"
                 : "=r"(r0), "=r"(r1), "=r"(r2), "=r"(r3) : "r"(a));
}
__device__ __forceinline__ void mma16816(float* c, const u32* a, u32 b0, u32 b1) {
    asm volatile("mma.sync.aligned.m16n8k16.row.col.f32.bf16.bf16.f32 "
                 "{%0,%1,%2,%3}, {%4,%5,%6,%7}, {%8,%9}, {%0,%1,%2,%3};"
                 : "+f"(c[0]), "+f"(c[1]), "+f"(c[2]), "+f"(c[3])
                 : "r"(a[0]), "r"(a[1]), "r"(a[2]), "r"(a[3]), "r"(b0), "r"(b1));
}
__device__ __forceinline__ u32 pack_bf(float lo, float hi) {  // lo -> bits[0:16)
    u32 r;
    asm("cvt.rn.bf16x2.f32 %0, %1, %2;" : "=r"(r) : "f"(hi), "f"(lo));
    return r;
}
__device__ __forceinline__ u32 min2bf(u32 a, u32 b) {
    u32 r;
    asm("min.bf16x2 %0, %1, %2;" : "=r"(r) : "r"(a), "r"(b));
    return r;
}
__device__ __forceinline__ float bf_lo(u32 w) { return __uint_as_float(w << 16); }
__device__ __forceinline__ float bf_hi(u32 w) { return __uint_as_float(w & 0xFFFF0000u); }
__device__ __forceinline__ u32 fkey(float f) {   // orderable-uint encode
    u32 b = __float_as_uint(f);
    return (b & 0x80000000u) ? ~b : (b | 0x80000000u);
}

// ============================================================
// Kernel 1: exact norms (strict sequential fp32 chains) + inits
// ============================================================
__global__ __launch_bounds__(256) void norms_kernel(const float* __restrict__ x,
                                                    const float* __restrict__ cb) {
    int blk = blockIdx.x;
    if (blk < 32) {
        int k = blk * 256 + threadIdx.x;
        const float* p = cb + (size_t)k * DD;
        float s = 0.f;
#pragma unroll 8
        for (int d = 0; d < DD; ++d) { float v = p[d]; s = __fadd_rn(s, __fmul_rn(v, v)); }
        g_cnorm[k] = s;
    } else {
        int n  = (blk - 32) * 256 + threadIdx.x;
        int b  = n >> 10, hw = n & (HW - 1);
        const float* p = x + (size_t)b * IMG + hw;
        float s = 0.f;
#pragma unroll 8
        for (int d = 0; d < DD; ++d) { float v = p[(size_t)d * HW]; s = __fadd_rn(s, __fmul_rn(v, v)); }
        g_xnorm[n] = s;
        g_dmin[n]  = 0xFFFFFFFFu;
        g_ccnt[n]  = 0;
    }
}

// ============================================================
// Kernel 2: convert x and cb to bf16 once
// ============================================================
__global__ __launch_bounds__(256) void convert_kernel(const float* __restrict__ x,
                                                      const float* __restrict__ cb) {
    size_t i = ((size_t)blockIdx.x * 256 + threadIdx.x) * 8;
    const float4* s;
    __nv_bfloat16* d;
    if (i < (size_t)NTOK * DD) { s = (const float4*)(x + i);              d = g_xb + i; }
    else { size_t j = i - (size_t)NTOK * DD; s = (const float4*)(cb + j); d = g_cbb + j; }
    float4 v0 = s[0], v1 = s[1];
    uint4 w;
    w.x = pack_bf(v0.x, v0.y); w.y = pack_bf(v0.z, v0.w);
    w.z = pack_bf(v1.x, v1.y); w.w = pack_bf(v1.z, v1.w);
    *(uint4*)d = w;
}

// ============================================================
// Kernel 3: HMMA bf16 prescreen GEMM (mma.sync.m16n8k16).
// CTA 128 codes x 256 tokens, 512 threads (4 wm x 4 wn warps).
// Epilogue: 8-code-group mins (shuffle-reduced, bf16) -> g_gmin,
// plus per-token global min atomics. NO full d-tilde materialization.
// ============================================================
__global__ __launch_bounds__(512, 1) void gemm_kernel() {
    __shared__ __align__(16) char sm[49152];   // A 2x8KB @0, B 2x16KB @16384
    const u32 smU = smem_u32(sm);
    const int tid  = threadIdx.x;
    const int lane = tid & 31;
    const int wid  = tid >> 5;
    const int wm   = wid & 3;      // code group (32 codes)
    const int wn   = wid >> 2;     // token group (64 tokens)

    const int code0 = (blockIdx.x & 63) * CTM;
    const int tok0  = (blockIdx.x >> 6) * CTN;
    const int bimg  = tok0 >> 10;
    const int hw0   = tok0 & (HW - 1);

    // A loader
    const int arow = tid >> 2, ac = tid & 3;
    const __nv_bfloat16* aG = g_cbb + (size_t)(code0 + arow) * DD + ac * 8;
    const u32 aOff = (u32)arow * 64u + (u32)((ac ^ ((arow >> 1) & 3))) * 16u;
    // B loader
    const int bd = tid >> 4, bc = tid & 15;
    const __nv_bfloat16* bG = g_xb + (size_t)bimg * IMG + hw0 + (size_t)bd * HW + bc * 8;
    const u32 bOff0 = 16384u + (u32)bd * 512u + (u32)((bc        ^ (bd & 7))) * 16u;
    const u32 bOff1 = 16384u + (u32)bd * 512u + (u32)(((bc + 16) ^ (bd & 7))) * 16u;

    float acc[2][8][4];
#pragma unroll
    for (int mi = 0; mi < 2; ++mi)
#pragma unroll
        for (int nt = 0; nt < 8; ++nt)
#pragma unroll
            for (int q = 0; q < 4; ++q) acc[mi][nt][q] = 0.f;

    uint4 aR  = *(const uint4*)aG;
    uint4 bR0 = *(const uint4*)bG;
    uint4 bR1 = *(const uint4*)(bG + 128);
    *(uint4*)(sm + aOff)  = aR;
    *(uint4*)(sm + bOff0) = bR0;
    *(uint4*)(sm + bOff1) = bR1;
    __syncthreads();

    const int sa = ((lane & 15) >> 1) & 3;
    const int sb = lane & 7;
    const u32 aFragBase = smU + (u32)(wm * 32 + (lane & 15)) * 64u;
    const u32 bFragBase = smU + 16384u + (u32)(lane & 15) * 512u;

    for (int ch = 0; ch < NCH; ++ch) {
        const int p = ch & 1;
        if (ch < NCH - 1) {
            aR  = *(const uint4*)(aG + (ch + 1) * CK);
            bR0 = *(const uint4*)(bG + (size_t)(ch + 1) * CK * HW);
            bR1 = *(const uint4*)(bG + (size_t)(ch + 1) * CK * HW + 128);
        }
#pragma unroll
        for (int kk = 0; kk < 2; ++kk) {
            u32 a0[4], a1[4];
            const u32 aTop = (u32)(((kk * 2 + (lane >> 4)) ^ sa)) * 16u + (u32)p * 8192u;
            ldsm4(a0[0], a0[1], a0[2], a0[3], aFragBase + aTop);
            ldsm4(a1[0], a1[1], a1[2], a1[3], aFragBase + 1024u + aTop);
            const u32 bRow = (u32)p * 16384u + (u32)(kk * 16) * 512u;
#pragma unroll
            for (int np = 0; np < 4; ++np) {
                u32 b0, b1, b2, b3;
                const u32 c = (u32)(((wn * 8 + np * 2 + (lane >> 4)) ^ sb)) * 16u;
                ldsm4t(b0, b1, b2, b3, bFragBase + bRow + c);
                mma16816(acc[0][2 * np],     a0, b0, b1);
                mma16816(acc[0][2 * np + 1], a0, b2, b3);
                mma16816(acc[1][2 * np],     a1, b0, b1);
                mma16816(acc[1][2 * np + 1], a1, b2, b3);
            }
        }
        if (ch < NCH - 1) {
            const u32 q = (u32)(p ^ 1);
            __syncthreads();
            *(uint4*)(sm + q * 8192u  + aOff)  = aR;
            *(uint4*)(sm + q * 16384u + bOff0) = bR0;
            *(uint4*)(sm + q * 16384u + bOff1) = bR1;
            __syncthreads();
        }
    }

    // ---- epilogue: 8-code group mins + per-token global min ----
    float tmn[8][2];
#pragma unroll
    for (int nt = 0; nt < 8; ++nt) { tmn[nt][0] = 3.4e38f; tmn[nt][1] = 3.4e38f; }

#pragma unroll
    for (int mi = 0; mi < 2; ++mi)
#pragma unroll
        for (int h = 0; h < 2; ++h) {
            const int cbase = code0 + wm * 32 + mi * 16 + h * 8;  // + (lane>>2)
            const float cn = g_cnorm[cbase + (lane >> 2)];
            float gm[8][2];
#pragma unroll
            for (int nt = 0; nt < 8; ++nt) {
                // bf16-rounded d-tilde (round-trip through bf16 for consistency)
                u32 w = pack_bf(fmaf(-2.f, acc[mi][nt][h * 2 + 0], cn),
                                fmaf(-2.f, acc[mi][nt][h * 2 + 1], cn));
                float f0 = bf_lo(w), f1 = bf_hi(w);
                // group min across the 8 codes (lane>>2 lanes; xor 4/8/16)
#pragma unroll
                for (int off = 4; off <= 16; off <<= 1) {
                    f0 = fminf(f0, __shfl_xor_sync(0xffffffffu, f0, off));
                    f1 = fminf(f1, __shfl_xor_sync(0xffffffffu, f1, off));
                }
                gm[nt][0] = f0; gm[nt][1] = f1;
                tmn[nt][0] = fminf(tmn[nt][0], f0);
                tmn[nt][1] = fminf(tmn[nt][1], f1);
            }
            if (lane < 4) {
                const int g = cbase >> 3;
                __nv_bfloat16* dst = g_gmin + (size_t)g * NTOK + tok0 + wn * 64 + 2 * lane;
#pragma unroll
                for (int nt = 0; nt < 8; ++nt)
                    *(u32*)(dst + nt * 8) = pack_bf(gm[nt][0], gm[nt][1]);
            }
        }
    if (lane < 4) {
#pragma unroll
        for (int nt = 0; nt < 8; ++nt) {
            int t = tok0 + wn * 64 + nt * 8 + 2 * lane;
            atomicMin(&g_dmin[t],     fkey(tmn[nt][0]));
            atomicMin(&g_dmin[t + 1], fkey(tmn[nt][1]));
        }
    }
}

// ============================================================
// Kernel 4: candidate-group collection from the 33.5MB pyramid.
// grid 256 = 8 token-blocks(2048) x 32 group-slices(32 groups).
// Thread scans 8 tokens (uint4) with min.bf16x2 fast-path.
// ============================================================
__global__ __launch_bounds__(256) void collect_kernel() {
    const int tok = (blockIdx.x & 7) * 2048 + threadIdx.x * 8;
    const int g0  = (blockIdx.x >> 3) * 32;

    float thr[8];
#pragma unroll
    for (int i = 0; i < 8; ++i) {
        u32 key = g_dmin[tok + i];
        u32 mb  = (key & 0x80000000u) ? (key ^ 0x80000000u) : ~key;
        thr[i] = __uint_as_float(mb) + EPS_WIN;
    }
    const float te = fmaxf(fmaxf(thr[0], thr[2]), fmaxf(thr[4], thr[6]));
    const float to = fmaxf(fmaxf(thr[1], thr[3]), fmaxf(thr[5], thr[7]));

    const uint4* __restrict__ base =
        (const uint4*)(g_gmin + tok) + (size_t)g0 * (NTOK / 8);
#pragma unroll 4
    for (int gi = 0; gi < 32; ++gi) {
        uint4 v = base[(size_t)gi * (NTOK / 8)];
        u32 m = min2bf(min2bf(v.x, v.y), min2bf(v.z, v.w));
        if (bf_lo(m) <= te || bf_hi(m) <= to) {          // rare fast-path trigger
            const int g = g0 + gi;
            const u32* wp = (const u32*)&v;
#pragma unroll
            for (int q = 0; q < 4; ++q) {
                u32 w = wp[q];
                if (bf_lo(w) <= thr[2 * q]) {
                    int t = tok + 2 * q;
                    int p = atomicAdd(&g_ccnt[t], 1);
                    if (p < CAP_G) g_cand[t * CAP_G + p] = g;
                }
                if (bf_hi(w) <= thr[2 * q + 1]) {
                    int t = tok + 2 * q + 1;
                    int p = atomicAdd(&g_ccnt[t], 1);
                    if (p < CAP_G) g_cand[t * CAP_G + p] = g;
                }
            }
        }
    }
}

// ============================================================
// Kernel 5: EXACT rescore (bit-exact ascending-d chain, reference
// rounding, lex-min (d,k)). Warp per token; 4 groups x 8 codes per
// pass; full-scan fallback on overflow.
// ============================================================
__global__ __launch_bounds__(256) void rescore_kernel(const float* __restrict__ x,
                                                      const float* __restrict__ cb) {
    __shared__ float xs[8][DD];
    const int tid = threadIdx.x, w = tid >> 5, lane = tid & 31;
    const int n = blockIdx.x * 8 + w;
    const int b = n >> 10, hw = n & (HW - 1);
    const float* xp = x + (size_t)b * IMG + hw;
#pragma unroll
    for (int d = lane; d < DD; d += 32) xs[w][d] = xp[(size_t)d * HW];
    __syncwarp();

    const int cnt = g_ccnt[n];
    const float xn = g_xnorm[n];
    float bv = 3.4e38f;
    int   bi = 0x7FFFFFFF;

    if (cnt <= CAP_G) {
        for (int ci = lane >> 3; ci < cnt; ci += 4) {
            int k = g_cand[n * CAP_G + ci] * 8 + (lane & 7);
            const float* cp = cb + (size_t)k * DD;
            float m = 0.f;
#pragma unroll 8
            for (int d = 0; d < DD; ++d) m = fmaf(xs[w][d], cp[d], m);
            float dd = __fsub_rn(__fadd_rn(xn, g_cnorm[k]), 2.0f * m);
            if (dd < bv || (dd == bv && k < bi)) { bv = dd; bi = k; }
        }
    } else {   // overflow fallback: exact full scan
        for (int k = lane; k < KC; k += 32) {
            const float* cp = cb + (size_t)k * DD;
            float m = 0.f;
#pragma unroll 8
            for (int d = 0; d < DD; ++d) m = fmaf(xs[w][d], cp[d], m);
            float dd = __fsub_rn(__fadd_rn(xn, g_cnorm[k]), 2.0f * m);
            if (dd < bv || (dd == bv && k < bi)) { bv = dd; bi = k; }
        }
    }
#pragma unroll
    for (int off = 16; off; off >>= 1) {
        float ov = __shfl_xor_sync(0xffffffffu, bv, off);
        int   ob = __shfl_xor_sync(0xffffffffu, bi, off);
        if (ov < bv || (ov == bv && ob < bi)) { bv = ov; bi = ob; }
    }
    if (lane == 0) g_idx[n] = bi;
}

// ============================================================
// Kernel 6: gather quant, straight-through output, loss partial.
// ============================================================
__global__ __launch_bounds__(256) void epi_kernel(const float* __restrict__ x,
                                                  const float* __restrict__ cb,
                                                  float* __restrict__ out) {
    __shared__ int   sidx[64];
    __shared__ float swarp[8];
    const int tid  = threadIdx.x;
    const int tok0 = blockIdx.x * 64;
    const int bimg = tok0 >> 10;
    const int hw0  = tok0 & (HW - 1);

    if (tid < 64) sidx[tid] = g_idx[tok0 + tid];
    __syncthreads();

    const int m  = tid & 63;
    const int dh = tid >> 6;
    const size_t base = (size_t)bimg * IMG + hw0 + m;
    const long long crow = (long long)sidx[m] * DD;

    float lsum = 0.f;
#pragma unroll 8
    for (int d0 = 0; d0 < DD; d0 += 4) {
        int d = d0 + dh;
        float q  = cb[crow + d];
        size_t off = base + (size_t)d * HW;
        float xv = x[off];
        float t  = __fsub_rn(q, xv);
        out[off] = __fadd_rn(xv, t);
        lsum = fmaf(t, t, lsum);
    }
#pragma unroll
    for (int off = 16; off; off >>= 1) lsum += __shfl_xor_sync(0xffffffffu, lsum, off);
    if ((tid & 31) == 0) swarp[tid >> 5] = lsum;
    __syncthreads();
    if (tid == 0) {
        float s = 0.f;
        for (int wq = 0; wq < 8; ++wq) s += swarp[wq];
        g_partial[blockIdx.x] = s;
    }
    if (tid < 64) out[OUT_ENC + tok0 + tid] = (float)sidx[tid];
}

// ============================================================
// Kernel 7: finalize loss
// ============================================================
__global__ __launch_bounds__(256) void fin_kernel(float* __restrict__ out) {
    __shared__ float sw[8];
    int tid = threadIdx.x;
    float s = g_partial[tid];
#pragma unroll
    for (int off = 16; off; off >>= 1) s += __shfl_xor_sync(0xffffffffu, s, off);
    if ((tid & 31) == 0) sw[tid >> 5] = s;
    __syncthreads();
    if (tid == 0) {
        float tot = 0.f;
        for (int wq = 0; wq < 8; ++wq) tot += sw[wq];
        float mse = tot / 4194304.0f;
        out[OUT_LOSS] = __fadd_rn(mse, __fmul_rn(0.25f, mse));
    }
}

// ============================================================
extern "C" void kernel_launch(void* const* d_in, const int* in_sizes, int n_in,
                              void* d_out, int out_size) {
    const float* x  = (const float*)d_in[0];   // [16,256,32,32] fp32
    const float* cb = (const float*)d_in[1];   // [8192,256] fp32
    float* out = (float*)d_out;

    norms_kernel<<<96, 256>>>(x, cb);
    convert_kernel<<<3072, 256>>>(x, cb);
    gemm_kernel<<<4096, 512>>>();
    collect_kernel<<<256, 256>>>();
    rescore_kernel<<<NTOK / 8, 256>>>(x, cb);
    epi_kernel<<<256, 256>>>(x, cb, out);
    fin_kernel<<<1, 256>>>(out);
}

// round 10
// speedup vs baseline: 13.4468x; 13.4468x over previous
#include <cuda_runtime.h>
#include <cuda_bf16.h>

// Problem constants
#define NTOK 16384      // B*H*W
#define KC   8192
#define DD   256
#define IMG  262144     // C*H*W
#define HW   1024

#define OUT_LOSS 4194304
#define OUT_ENC  4194305

// GEMM tiling: M = codes, N = tokens
#define CTM 128
#define CTN 256
#define CK  32
#define NCH (DD / CK)   // 8

#define EPS_WIN  1.0e-3f
#define CAND_CAP 64

typedef unsigned int u32;

// -------- scratch (device globals; no allocation allowed) --------
__device__ float g_cnorm[KC];
__device__ float g_xnorm[NTOK];
__device__ int   g_idx[NTOK];
__device__ float g_partial[256];
__device__ u32   g_dmin[NTOK];
__device__ int   g_ccnt[NTOK];
__device__ int   g_cand[NTOK * CAND_CAP];
__device__ __align__(16) __nv_bfloat16 g_xb[NTOK * DD];     // x [b][d][hw] bf16
__device__ __align__(16) __nv_bfloat16 g_cbb[KC * DD];      // [code][d] bf16
__device__ __align__(16) __nv_bfloat16 g_dtil[134217728];   // [code][token] 256MB

// -------- helpers --------
__device__ __forceinline__ u32 smem_u32(const void* p) {
    u32 a;
    asm("{ .reg .u64 t; cvta.to.shared.u64 t, %1; cvt.u32.u64 %0, t; }" : "=r"(a) : "l"(p));
    return a;
}
__device__ __forceinline__ void ldsm4(u32& r0, u32& r1, u32& r2, u32& r3, u32 a) {
    asm volatile("ldmatrix.sync.aligned.m8n8.x4.shared.b16 {%0,%1,%2,%3}, [%4];"
                 : "=r"(r0), "=r"(r1), "=r"(r2), "=r"(r3) : "r"(a));
}
__device__ __forceinline__ void ldsm4t(u32& r0, u32& r1, u32& r2, u32& r3, u32 a) {
    asm volatile("ldmatrix.sync.aligned.m8n8.x4.trans.shared.b16 {%0,%1,%2,%3}, [%4];"
                 : "=r"(r0), "=r"(r1), "=r"(r2), "=r"(r3) : "r"(a));
}
__device__ __forceinline__ void mma16816(float* c, const u32* a, u32 b0, u32 b1) {
    asm volatile("mma.sync.aligned.m16n8k16.row.col.f32.bf16.bf16.f32 "
                 "{%0,%1,%2,%3}, {%4,%5,%6,%7}, {%8,%9}, {%0,%1,%2,%3};"
                 : "+f"(c[0]), "+f"(c[1]), "+f"(c[2]), "+f"(c[3])
                 : "r"(a[0]), "r"(a[1]), "r"(a[2]), "r"(a[3]), "r"(b0), "r"(b1));
}
__device__ __forceinline__ u32 pack_bf(float lo, float hi) {  // lo -> bits[0:16)
    u32 r;
    asm("cvt.rn.bf16x2.f32 %0, %1, %2;" : "=r"(r) : "f"(hi), "f"(lo));
    return r;
}
__device__ __forceinline__ u32 min2bf(u32 a, u32 b) {
    u32 r;
    asm("min.bf16x2 %0, %1, %2;" : "=r"(r) : "r"(a), "r"(b));
    return r;
}
__device__ __forceinline__ float bf_lo(u32 w) { return __uint_as_float(w << 16); }
__device__ __forceinline__ float bf_hi(u32 w) { return __uint_as_float(w & 0xFFFF0000u); }
__device__ __forceinline__ u32 fkey(float f) {   // orderable-uint encode
    u32 b = __float_as_uint(f);
    return (b & 0x80000000u) ? ~b : (b | 0x80000000u);
}

// ============================================================
// Kernel 1: exact norms (strict sequential fp32 chains) + inits
// ============================================================
__global__ __launch_bounds__(256) void norms_kernel(const float* __restrict__ x,
                                                    const float* __restrict__ cb) {
    int blk = blockIdx.x;
    if (blk < 32) {
        int k = blk * 256 + threadIdx.x;
        const float* p = cb + (size_t)k * DD;
        float s = 0.f;
#pragma unroll 8
        for (int d = 0; d < DD; ++d) { float v = p[d]; s = __fadd_rn(s, __fmul_rn(v, v)); }
        g_cnorm[k] = s;
    } else {
        int n  = (blk - 32) * 256 + threadIdx.x;
        int b  = n >> 10, hw = n & (HW - 1);
        const float* p = x + (size_t)b * IMG + hw;
        float s = 0.f;
#pragma unroll 8
        for (int d = 0; d < DD; ++d) { float v = p[(size_t)d * HW]; s = __fadd_rn(s, __fmul_rn(v, v)); }
        g_xnorm[n] = s;
        g_dmin[n]  = 0xFFFFFFFFu;
        g_ccnt[n]  = 0;
    }
}

// ============================================================
// Kernel 2: convert x and cb to bf16 once
// ============================================================
__global__ __launch_bounds__(256) void convert_kernel(const float* __restrict__ x,
                                                      const float* __restrict__ cb) {
    size_t i = ((size_t)blockIdx.x * 256 + threadIdx.x) * 8;
    const float4* s;
    __nv_bfloat16* d;
    if (i < (size_t)NTOK * DD) { s = (const float4*)(x + i);              d = g_xb + i; }
    else { size_t j = i - (size_t)NTOK * DD; s = (const float4*)(cb + j); d = g_cbb + j; }
    float4 v0 = s[0], v1 = s[1];
    uint4 w;
    w.x = pack_bf(v0.x, v0.y); w.y = pack_bf(v0.z, v0.w);
    w.z = pack_bf(v1.x, v1.y); w.w = pack_bf(v1.z, v1.w);
    *(uint4*)d = w;
}

// ============================================================
// Kernel 3: HMMA bf16 prescreen GEMM (round-8 exact; known-good).
// CTA 128 codes x 256 tokens, 512 threads (4 wm x 4 wn warps).
// Epilogue: dtil[code][token] = bf16(cn - 2*m), per-token min atomics.
// ============================================================
__global__ __launch_bounds__(512, 1) void gemm_kernel() {
    __shared__ __align__(16) char sm[49152];   // A 2x8KB @0, B 2x16KB @16384
    const u32 smU = smem_u32(sm);
    const int tid  = threadIdx.x;
    const int lane = tid & 31;
    const int wid  = tid >> 5;
    const int wm   = wid & 3;      // code group (32 codes)
    const int wn   = wid >> 2;     // token group (64 tokens)

    const int code0 = (blockIdx.x & 63) * CTM;
    const int tok0  = (blockIdx.x >> 6) * CTN;
    const int bimg  = tok0 >> 10;
    const int hw0   = tok0 & (HW - 1);

    const int arow = tid >> 2, ac = tid & 3;
    const __nv_bfloat16* aG = g_cbb + (size_t)(code0 + arow) * DD + ac * 8;
    const u32 aOff = (u32)arow * 64u + (u32)((ac ^ ((arow >> 1) & 3))) * 16u;
    const int bd = tid >> 4, bc = tid & 15;
    const __nv_bfloat16* bG = g_xb + (size_t)bimg * IMG + hw0 + (size_t)bd * HW + bc * 8;
    const u32 bOff0 = 16384u + (u32)bd * 512u + (u32)((bc        ^ (bd & 7))) * 16u;
    const u32 bOff1 = 16384u + (u32)bd * 512u + (u32)(((bc + 16) ^ (bd & 7))) * 16u;

    float acc[2][8][4];
#pragma unroll
    for (int mi = 0; mi < 2; ++mi)
#pragma unroll
        for (int nt = 0; nt < 8; ++nt)
#pragma unroll
            for (int q = 0; q < 4; ++q) acc[mi][nt][q] = 0.f;

    uint4 aR  = *(const uint4*)aG;
    uint4 bR0 = *(const uint4*)bG;
    uint4 bR1 = *(const uint4*)(bG + 128);
    *(uint4*)(sm + aOff)  = aR;
    *(uint4*)(sm + bOff0) = bR0;
    *(uint4*)(sm + bOff1) = bR1;
    __syncthreads();

    const int sa = ((lane & 15) >> 1) & 3;
    const int sb = lane & 7;
    const u32 aFragBase = smU + (u32)(wm * 32 + (lane & 15)) * 64u;
    const u32 bFragBase = smU + 16384u + (u32)(lane & 15) * 512u;

    for (int ch = 0; ch < NCH; ++ch) {
        const int p = ch & 1;
        if (ch < NCH - 1) {
            aR  = *(const uint4*)(aG + (ch + 1) * CK);
            bR0 = *(const uint4*)(bG + (size_t)(ch + 1) * CK * HW);
            bR1 = *(const uint4*)(bG + (size_t)(ch + 1) * CK * HW + 128);
        }
#pragma unroll
        for (int kk = 0; kk < 2; ++kk) {
            u32 a0[4], a1[4];
            const u32 aTop = (u32)(((kk * 2 + (lane >> 4)) ^ sa)) * 16u + (u32)p * 8192u;
            ldsm4(a0[0], a0[1], a0[2], a0[3], aFragBase + aTop);
            ldsm4(a1[0], a1[1], a1[2], a1[3], aFragBase + 1024u + aTop);
            const u32 bRow = (u32)p * 16384u + (u32)(kk * 16) * 512u;
#pragma unroll
            for (int np = 0; np < 4; ++np) {
                u32 b0, b1, b2, b3;
                const u32 c = (u32)(((wn * 8 + np * 2 + (lane >> 4)) ^ sb)) * 16u;
                ldsm4t(b0, b1, b2, b3, bFragBase + bRow + c);
                mma16816(acc[0][2 * np],     a0, b0, b1);
                mma16816(acc[0][2 * np + 1], a0, b2, b3);
                mma16816(acc[1][2 * np],     a1, b0, b1);
                mma16816(acc[1][2 * np + 1], a1, b2, b3);
            }
        }
        if (ch < NCH - 1) {
            const u32 q = (u32)(p ^ 1);
            __syncthreads();
            *(uint4*)(sm + q * 8192u  + aOff)  = aR;
            *(uint4*)(sm + q * 16384u + bOff0) = bR0;
            *(uint4*)(sm + q * 16384u + bOff1) = bR1;
            __syncthreads();
        }
    }

    // ---- epilogue: dtil store + per-token min (round-8 exact) ----
    float tmn[8][2];
#pragma unroll
    for (int nt = 0; nt < 8; ++nt) { tmn[nt][0] = 3.4e38f; tmn[nt][1] = 3.4e38f; }
#pragma unroll
    for (int mi = 0; mi < 2; ++mi)
#pragma unroll
        for (int h = 0; h < 2; ++h) {
            const int code = code0 + wm * 32 + mi * 16 + (lane >> 2) + h * 8;
            const float cn = g_cnorm[code];
            __nv_bfloat16* dst = g_dtil + (size_t)code * NTOK + tok0 + wn * 64 + 2 * (lane & 3);
#pragma unroll
            for (int nt = 0; nt < 8; ++nt) {
                float dv0 = fmaf(-2.f, acc[mi][nt][h * 2 + 0], cn);
                float dv1 = fmaf(-2.f, acc[mi][nt][h * 2 + 1], cn);
                u32 w = pack_bf(dv0, dv1);
                *(u32*)(dst + (size_t)nt * 8) = w;
                tmn[nt][0] = fminf(tmn[nt][0], bf_lo(w));
                tmn[nt][1] = fminf(tmn[nt][1], bf_hi(w));
            }
        }
#pragma unroll
    for (int nt = 0; nt < 8; ++nt)
#pragma unroll
        for (int off = 16; off >= 4; off >>= 1) {
            tmn[nt][0] = fminf(tmn[nt][0], __shfl_xor_sync(0xffffffffu, tmn[nt][0], off));
            tmn[nt][1] = fminf(tmn[nt][1], __shfl_xor_sync(0xffffffffu, tmn[nt][1], off));
        }
    if (lane < 4) {
#pragma unroll
        for (int nt = 0; nt < 8; ++nt) {
            int t = tok0 + wn * 64 + nt * 8 + 2 * lane;
            atomicMin(&g_dmin[t],     fkey(tmn[nt][0]));
            atomicMin(&g_dmin[t + 1], fkey(tmn[nt][1]));
        }
    }
}

// ============================================================
// Kernel 4: candidate collection — COALESCED uint4 row scan.
// grid 1024 = 8 token-blocks(2048 tokens) x 128 code-slices(64 codes).
// Thread owns 8 tokens; per code row: one uint4 + min.bf16x2 fast path.
// ============================================================
__global__ __launch_bounds__(256) void collect_kernel() {
    const int tok = (blockIdx.x & 7) * 2048 + threadIdx.x * 8;
    const int k0  = (blockIdx.x >> 3) * 64;

    float thr[8];
#pragma unroll
    for (int i = 0; i < 8; ++i) {
        u32 key = g_dmin[tok + i];
        u32 mb  = (key & 0x80000000u) ? (key ^ 0x80000000u) : ~key;
        thr[i] = __uint_as_float(mb) + EPS_WIN;
    }
    const float te = fmaxf(fmaxf(thr[0], thr[2]), fmaxf(thr[4], thr[6]));
    const float to = fmaxf(fmaxf(thr[1], thr[3]), fmaxf(thr[5], thr[7]));

    const uint4* __restrict__ base =
        (const uint4*)(g_dtil + tok) + (size_t)k0 * (NTOK / 8);
#pragma unroll 8
    for (int ki = 0; ki < 64; ++ki) {
        uint4 v = base[(size_t)ki * (NTOK / 8)];
        u32 m = min2bf(min2bf(v.x, v.y), min2bf(v.z, v.w));
        if (bf_lo(m) <= te || bf_hi(m) <= to) {          // rare fast-path trigger
            const int k = k0 + ki;
            const u32* wp = (const u32*)&v;
#pragma unroll
            for (int q = 0; q < 4; ++q) {
                u32 w = wp[q];
                if (bf_lo(w) <= thr[2 * q]) {
                    int t = tok + 2 * q;
                    int p = atomicAdd(&g_ccnt[t], 1);
                    if (p < CAND_CAP) g_cand[t * CAND_CAP + p] = k;
                }
                if (bf_hi(w) <= thr[2 * q + 1]) {
                    int t = tok + 2 * q + 1;
                    int p = atomicAdd(&g_ccnt[t], 1);
                    if (p < CAND_CAP) g_cand[t * CAND_CAP + p] = k;
                }
            }
        }
    }
}

// ============================================================
// Kernel 5: EXACT rescore (bit-exact ascending-d chain, reference
// rounding, lex-min (d,k) = jnp.argmin). Warp per token; full-scan
// fallback on candidate overflow.
// ============================================================
__global__ __launch_bounds__(256) void rescore_kernel(const float* __restrict__ x,
                                                      const float* __restrict__ cb) {
    __shared__ float xs[8][DD];
    const int tid = threadIdx.x, w = tid >> 5, lane = tid & 31;
    const int n = blockIdx.x * 8 + w;
    const int b = n >> 10, hw = n & (HW - 1);
    const float* xp = x + (size_t)b * IMG + hw;
#pragma unroll
    for (int d = lane; d < DD; d += 32) xs[w][d] = xp[(size_t)d * HW];
    __syncwarp();

    const int cnt = g_ccnt[n];
    const float xn = g_xnorm[n];
    float bv = 3.4e38f;
    int   bi = 0x7FFFFFFF;

    if (cnt <= CAND_CAP) {
        for (int ci = lane; ci < cnt; ci += 32) {
            int k = g_cand[n * CAND_CAP + ci];
            const float* cp = cb + (size_t)k * DD;
            float m = 0.f;
#pragma unroll 8
            for (int d = 0; d < DD; ++d) m = fmaf(xs[w][d], cp[d], m);
            float dd = __fsub_rn(__fadd_rn(xn, g_cnorm[k]), 2.0f * m);
            if (dd < bv || (dd == bv && k < bi)) { bv = dd; bi = k; }
        }
    } else {   // overflow fallback: exact full scan
        for (int k = lane; k < KC; k += 32) {
            const float* cp = cb + (size_t)k * DD;
            float m = 0.f;
#pragma unroll 8
            for (int d = 0; d < DD; ++d) m = fmaf(xs[w][d], cp[d], m);
            float dd = __fsub_rn(__fadd_rn(xn, g_cnorm[k]), 2.0f * m);
            if (dd < bv || (dd == bv && k < bi)) { bv = dd; bi = k; }
        }
    }
#pragma unroll
    for (int off = 16; off; off >>= 1) {
        float ov = __shfl_xor_sync(0xffffffffu, bv, off);
        int   ob = __shfl_xor_sync(0xffffffffu, bi, off);
        if (ov < bv || (ov == bv && ob < bi)) { bv = ov; bi = ob; }
    }
    if (lane == 0) g_idx[n] = bi;
}

// ============================================================
// Kernel 6: gather quant, straight-through output, loss partial.
// ============================================================
__global__ __launch_bounds__(256) void epi_kernel(const float* __restrict__ x,
                                                  const float* __restrict__ cb,
                                                  float* __restrict__ out) {
    __shared__ int   sidx[64];
    __shared__ float swarp[8];
    const int tid  = threadIdx.x;
    const int tok0 = blockIdx.x * 64;
    const int bimg = tok0 >> 10;
    const int hw0  = tok0 & (HW - 1);

    if (tid < 64) sidx[tid] = g_idx[tok0 + tid];
    __syncthreads();

    const int m  = tid & 63;
    const int dh = tid >> 6;
    const size_t base = (size_t)bimg * IMG + hw0 + m;
    const long long crow = (long long)sidx[m] * DD;

    float lsum = 0.f;
#pragma unroll 8
    for (int d0 = 0; d0 < DD; d0 += 4) {
        int d = d0 + dh;
        float q  = cb[crow + d];
        size_t off = base + (size_t)d * HW;
        float xv = x[off];
        float t  = __fsub_rn(q, xv);
        out[off] = __fadd_rn(xv, t);
        lsum = fmaf(t, t, lsum);
    }
#pragma unroll
    for (int off = 16; off; off >>= 1) lsum += __shfl_xor_sync(0xffffffffu, lsum, off);
    if ((tid & 31) == 0) swarp[tid >> 5] = lsum;
    __syncthreads();
    if (tid == 0) {
        float s = 0.f;
        for (int wq = 0; wq < 8; ++wq) s += swarp[wq];
        g_partial[blockIdx.x] = s;
    }
    if (tid < 64) out[OUT_ENC + tok0 + tid] = (float)sidx[tid];
}

// ============================================================
// Kernel 7: finalize loss
// ============================================================
__global__ __launch_bounds__(256) void fin_kernel(float* __restrict__ out) {
    __shared__ float sw[8];
    int tid = threadIdx.x;
    float s = g_partial[tid];
#pragma unroll
    for (int off = 16; off; off >>= 1) s += __shfl_xor_sync(0xffffffffu, s, off);
    if ((tid & 31) == 0) sw[tid >> 5] = s;
    __syncthreads();
    if (tid == 0) {
        float tot = 0.f;
        for (int wq = 0; wq < 8; ++wq) tot += sw[wq];
        float mse = tot / 4194304.0f;
        out[OUT_LOSS] = __fadd_rn(mse, __fmul_rn(0.25f, mse));
    }
}

// ============================================================
extern "C" void kernel_launch(void* const* d_in, const int* in_sizes, int n_in,
                              void* d_out, int out_size) {
    const float* x  = (const float*)d_in[0];   // [16,256,32,32] fp32
    const float* cb = (const float*)d_in[1];   // [8192,256] fp32
    float* out = (float*)d_out;

    norms_kernel<<<96, 256>>>(x, cb);
    convert_kernel<<<3072, 256>>>(x, cb);
    gemm_kernel<<<4096, 512>>>();
    collect_kernel<<<1024, 256>>>();
    rescore_kernel<<<NTOK / 8, 256>>>(x, cb);
    epi_kernel<<<256, 256>>>(x, cb, out);
    fin_kernel<<<1, 256>>>(out);
}

// round 12
// speedup vs baseline: 14.7957x; 1.1003x over previous
#include <cuda_runtime.h>
#include <cuda_bf16.h>

// Problem constants
#define NTOK 16384      // B*H*W
#define KC   8192
#define DD   256
#define IMG  262144     // C*H*W
#define HW   1024

#define OUT_LOSS 4194304
#define OUT_ENC  4194305

// GEMM tiling: M = codes, N = tokens
#define CTM 128
#define CTN 256
#define CK  32
#define NCH (DD / CK)   // 8
#define NSTG 4          // cp.async pipeline stages
#define A_STG 8192      // bytes per A stage (128 x 64B)
#define B_STG 16384     // bytes per B stage (32 x 512B)
#define B_BASE (NSTG * A_STG)                 // 32768
#define GEMM_SMEM (B_BASE + NSTG * B_STG)     // 98304

#define EPS_WIN  1.0e-3f
#define CAND_CAP 64

typedef unsigned int u32;

// -------- scratch (device globals; no allocation allowed) --------
__device__ float g_cnorm[KC];
__device__ float g_xnorm[NTOK];
__device__ int   g_idx[NTOK];
__device__ float g_partial[256];
__device__ u32   g_dmin[NTOK];
__device__ int   g_ccnt[NTOK];
__device__ int   g_cand[NTOK * CAND_CAP];
__device__ __align__(16) __nv_bfloat16 g_xb[NTOK * DD];     // x [b][d][hw] bf16
__device__ __align__(16) __nv_bfloat16 g_cbb[KC * DD];      // [code][d] bf16
__device__ __align__(16) __nv_bfloat16 g_dtil[134217728];   // [code][token] 256MB

// -------- helpers --------
__device__ __forceinline__ u32 smem_u32(const void* p) {
    u32 a;
    asm("{ .reg .u64 t; cvta.to.shared.u64 t, %1; cvt.u32.u64 %0, t; }" : "=r"(a) : "l"(p));
    return a;
}
__device__ __forceinline__ void cpa(u32 dst, const void* src) {
    asm volatile("cp.async.cg.shared.global [%0], [%1], 16;" :: "r"(dst), "l"(src) : "memory");
}
#define CPC() asm volatile("cp.async.commit_group;" ::: "memory")
#define CPW(n) asm volatile("cp.async.wait_group %0;" :: "n"(n) : "memory")
__device__ __forceinline__ void ldsm4(u32& r0, u32& r1, u32& r2, u32& r3, u32 a) {
    asm volatile("ldmatrix.sync.aligned.m8n8.x4.shared.b16 {%0,%1,%2,%3}, [%4];"
                 : "=r"(r0), "=r"(r1), "=r"(r2), "=r"(r3) : "r"(a));
}
__device__ __forceinline__ void ldsm4t(u32& r0, u32& r1, u32& r2, u32& r3, u32 a) {
    asm volatile("ldmatrix.sync.aligned.m8n8.x4.trans.shared.b16 {%0,%1,%2,%3}, [%4];"
                 : "=r"(r0), "=r"(r1), "=r"(r2), "=r"(r3) : "r"(a));
}
__device__ __forceinline__ void mma16816(float* c, const u32* a, u32 b0, u32 b1) {
    asm volatile("mma.sync.aligned.m16n8k16.row.col.f32.bf16.bf16.f32 "
                 "{%0,%1,%2,%3}, {%4,%5,%6,%7}, {%8,%9}, {%0,%1,%2,%3};"
                 : "+f"(c[0]), "+f"(c[1]), "+f"(c[2]), "+f"(c[3])
                 : "r"(a[0]), "r"(a[1]), "r"(a[2]), "r"(a[3]), "r"(b0), "r"(b1));
}
__device__ __forceinline__ u32 pack_bf(float lo, float hi) {  // lo -> bits[0:16)
    u32 r;
    asm("cvt.rn.bf16x2.f32 %0, %1, %2;" : "=r"(r) : "f"(hi), "f"(lo));
    return r;
}
__device__ __forceinline__ u32 min2bf(u32 a, u32 b) {
    u32 r;
    asm("min.bf16x2 %0, %1, %2;" : "=r"(r) : "r"(a), "r"(b));
    return r;
}
__device__ __forceinline__ float bf_lo(u32 w) { return __uint_as_float(w << 16); }
__device__ __forceinline__ float bf_hi(u32 w) { return __uint_as_float(w & 0xFFFF0000u); }
__device__ __forceinline__ u32 fkey(float f) {   // orderable-uint encode
    u32 b = __float_as_uint(f);
    return (b & 0x80000000u) ? ~b : (b | 0x80000000u);
}

// ============================================================
// Kernel 1: exact norms (strict sequential fp32 chains) + inits
// ============================================================
__global__ __launch_bounds__(256) void norms_kernel(const float* __restrict__ x,
                                                    const float* __restrict__ cb) {
    int blk = blockIdx.x;
    if (blk < 32) {
        int k = blk * 256 + threadIdx.x;
        const float* p = cb + (size_t)k * DD;
        float s = 0.f;
#pragma unroll 8
        for (int d = 0; d < DD; ++d) { float v = p[d]; s = __fadd_rn(s, __fmul_rn(v, v)); }
        g_cnorm[k] = s;
    } else {
        int n  = (blk - 32) * 256 + threadIdx.x;
        int b  = n >> 10, hw = n & (HW - 1);
        const float* p = x + (size_t)b * IMG + hw;
        float s = 0.f;
#pragma unroll 8
        for (int d = 0; d < DD; ++d) { float v = p[(size_t)d * HW]; s = __fadd_rn(s, __fmul_rn(v, v)); }
        g_xnorm[n] = s;
        g_dmin[n]  = 0xFFFFFFFFu;
        g_ccnt[n]  = 0;
    }
}

// ============================================================
// Kernel 2: convert x and cb to bf16 once
// ============================================================
__global__ __launch_bounds__(256) void convert_kernel(const float* __restrict__ x,
                                                      const float* __restrict__ cb) {
    size_t i = ((size_t)blockIdx.x * 256 + threadIdx.x) * 8;
    const float4* s;
    __nv_bfloat16* d;
    if (i < (size_t)NTOK * DD) { s = (const float4*)(x + i);              d = g_xb + i; }
    else { size_t j = i - (size_t)NTOK * DD; s = (const float4*)(cb + j); d = g_cbb + j; }
    float4 v0 = s[0], v1 = s[1];
    uint4 w;
    w.x = pack_bf(v0.x, v0.y); w.y = pack_bf(v0.z, v0.w);
    w.z = pack_bf(v1.x, v1.y); w.w = pack_bf(v1.z, v1.w);
    *(uint4*)d = w;
}

// ============================================================
// Kernel 3: HMMA bf16 prescreen GEMM, 4-stage cp.async pipeline.
// CTA 128 codes x 256 tokens, 512 threads (4 wm x 4 wn warps).
// FIX vs round 11: an empty commit_group is issued on iterations
// with no load, so wait_group<2> keeps advancing through the tail
// (otherwise chunks 6,7 were unguaranteed -> racy stale reads).
// Epilogue: dtil[code][token] = bf16(cn - 2*m), per-token min atomics.
// ============================================================
__global__ __launch_bounds__(512, 1) void gemm_kernel() {
    extern __shared__ __align__(16) char sm[];
    const u32 smU = smem_u32(sm);
    const int tid  = threadIdx.x;
    const int lane = tid & 31;
    const int wid  = tid >> 5;
    const int wm   = wid & 3;      // code group (32 codes)
    const int wn   = wid >> 2;     // token group (64 tokens)

    const int code0 = (blockIdx.x & 63) * CTM;
    const int tok0  = (blockIdx.x >> 6) * CTN;
    const int bimg  = tok0 >> 10;
    const int hw0   = tok0 & (HW - 1);

    const int arow = tid >> 2, ac = tid & 3;
    const __nv_bfloat16* aG = g_cbb + (size_t)(code0 + arow) * DD + ac * 8;
    const u32 aOff = (u32)arow * 64u + (u32)((ac ^ ((arow >> 1) & 3))) * 16u;
    const int bd = tid >> 4, bc = tid & 15;
    const __nv_bfloat16* bG = g_xb + (size_t)bimg * IMG + hw0 + (size_t)bd * HW + bc * 8;
    const u32 bOff0 = (u32)bd * 512u + (u32)((bc        ^ (bd & 7))) * 16u;
    const u32 bOff1 = (u32)bd * 512u + (u32)(((bc + 16) ^ (bd & 7))) * 16u;

    float acc[2][8][4];
#pragma unroll
    for (int mi = 0; mi < 2; ++mi)
#pragma unroll
        for (int nt = 0; nt < 8; ++nt)
#pragma unroll
            for (int q = 0; q < 4; ++q) acc[mi][nt][q] = 0.f;

#define LOAD_CHUNK(ch) do {                                                   \
        const u32 _st = (u32)((ch) & (NSTG - 1));                             \
        cpa(smU + _st * A_STG + aOff, aG + (ch) * CK);                        \
        cpa(smU + B_BASE + _st * B_STG + bOff0, bG + (size_t)(ch) * CK * HW); \
        cpa(smU + B_BASE + _st * B_STG + bOff1,                               \
            bG + (size_t)(ch) * CK * HW + 128);                               \
        CPC();                                                                \
    } while (0)

    LOAD_CHUNK(0);
    LOAD_CHUNK(1);
    LOAD_CHUNK(2);

    const int sa = ((lane & 15) >> 1) & 3;
    const int sb = lane & 7;
    const u32 aFragBase = smU + (u32)(wm * 32 + (lane & 15)) * 64u;
    const u32 bFragBase = smU + B_BASE + (u32)(lane & 15) * 512u;

    for (int ch = 0; ch < NCH; ++ch) {
        CPW(2);                    // with per-iter commits: chunks 0..ch landed
        __syncthreads();           // stage (ch-1)&3 readers all done
        if (ch + 3 < NCH) LOAD_CHUNK(ch + 3);
        else              CPC();   // EMPTY group: keeps wait_group advancing

        const u32 st = (u32)(ch & (NSTG - 1));
#pragma unroll
        for (int kk = 0; kk < 2; ++kk) {
            u32 a0[4], a1[4];
            const u32 aTop = (u32)(((kk * 2 + (lane >> 4)) ^ sa)) * 16u + st * A_STG;
            ldsm4(a0[0], a0[1], a0[2], a0[3], aFragBase + aTop);
            ldsm4(a1[0], a1[1], a1[2], a1[3], aFragBase + 1024u + aTop);
            const u32 bRow = st * B_STG + (u32)(kk * 16) * 512u;
#pragma unroll
            for (int np = 0; np < 4; ++np) {
                u32 b0, b1, b2, b3;
                const u32 c = (u32)(((wn * 8 + np * 2 + (lane >> 4)) ^ sb)) * 16u;
                ldsm4t(b0, b1, b2, b3, bFragBase + bRow + c);
                mma16816(acc[0][2 * np],     a0, b0, b1);
                mma16816(acc[0][2 * np + 1], a0, b2, b3);
                mma16816(acc[1][2 * np],     a1, b0, b1);
                mma16816(acc[1][2 * np + 1], a1, b2, b3);
            }
        }
    }
#undef LOAD_CHUNK

    // ---- epilogue: dtil store + per-token min (round-10 exact) ----
    float tmn[8][2];
#pragma unroll
    for (int nt = 0; nt < 8; ++nt) { tmn[nt][0] = 3.4e38f; tmn[nt][1] = 3.4e38f; }
#pragma unroll
    for (int mi = 0; mi < 2; ++mi)
#pragma unroll
        for (int h = 0; h < 2; ++h) {
            const int code = code0 + wm * 32 + mi * 16 + (lane >> 2) + h * 8;
            const float cn = g_cnorm[code];
            __nv_bfloat16* dst = g_dtil + (size_t)code * NTOK + tok0 + wn * 64 + 2 * (lane & 3);
#pragma unroll
            for (int nt = 0; nt < 8; ++nt) {
                float dv0 = fmaf(-2.f, acc[mi][nt][h * 2 + 0], cn);
                float dv1 = fmaf(-2.f, acc[mi][nt][h * 2 + 1], cn);
                u32 w = pack_bf(dv0, dv1);
                *(u32*)(dst + (size_t)nt * 8) = w;
                tmn[nt][0] = fminf(tmn[nt][0], bf_lo(w));
                tmn[nt][1] = fminf(tmn[nt][1], bf_hi(w));
            }
        }
#pragma unroll
    for (int nt = 0; nt < 8; ++nt)
#pragma unroll
        for (int off = 16; off >= 4; off >>= 1) {
            tmn[nt][0] = fminf(tmn[nt][0], __shfl_xor_sync(0xffffffffu, tmn[nt][0], off));
            tmn[nt][1] = fminf(tmn[nt][1], __shfl_xor_sync(0xffffffffu, tmn[nt][1], off));
        }
    if (lane < 4) {
#pragma unroll
        for (int nt = 0; nt < 8; ++nt) {
            int t = tok0 + wn * 64 + nt * 8 + 2 * lane;
            atomicMin(&g_dmin[t],     fkey(tmn[nt][0]));
            atomicMin(&g_dmin[t + 1], fkey(tmn[nt][1]));
        }
    }
}

// ============================================================
// Kernel 4: candidate collection — COALESCED uint4 row scan.
// (round-10 exact; measured 60us)
// ============================================================
__global__ __launch_bounds__(256) void collect_kernel() {
    const int tok = (blockIdx.x & 7) * 2048 + threadIdx.x * 8;
    const int k0  = (blockIdx.x >> 3) * 64;

    float thr[8];
#pragma unroll
    for (int i = 0; i < 8; ++i) {
        u32 key = g_dmin[tok + i];
        u32 mb  = (key & 0x80000000u) ? (key ^ 0x80000000u) : ~key;
        thr[i] = __uint_as_float(mb) + EPS_WIN;
    }
    const float te = fmaxf(fmaxf(thr[0], thr[2]), fmaxf(thr[4], thr[6]));
    const float to = fmaxf(fmaxf(thr[1], thr[3]), fmaxf(thr[5], thr[7]));

    const uint4* __restrict__ base =
        (const uint4*)(g_dtil + tok) + (size_t)k0 * (NTOK / 8);
#pragma unroll 8
    for (int ki = 0; ki < 64; ++ki) {
        uint4 v = base[(size_t)ki * (NTOK / 8)];
        u32 m = min2bf(min2bf(v.x, v.y), min2bf(v.z, v.w));
        if (bf_lo(m) <= te || bf_hi(m) <= to) {          // rare fast-path trigger
            const int k = k0 + ki;
            const u32* wp = (const u32*)&v;
#pragma unroll
            for (int q = 0; q < 4; ++q) {
                u32 w = wp[q];
                if (bf_lo(w) <= thr[2 * q]) {
                    int t = tok + 2 * q;
                    int p = atomicAdd(&g_ccnt[t], 1);
                    if (p < CAND_CAP) g_cand[t * CAND_CAP + p] = k;
                }
                if (bf_hi(w) <= thr[2 * q + 1]) {
                    int t = tok + 2 * q + 1;
                    int p = atomicAdd(&g_ccnt[t], 1);
                    if (p < CAND_CAP) g_cand[t * CAND_CAP + p] = k;
                }
            }
        }
    }
}

// ============================================================
// Kernel 5: EXACT rescore (bit-exact ascending-d chain, reference
// rounding, lex-min (d,k) = jnp.argmin). Warp per token; full-scan
// fallback on candidate overflow.
// ============================================================
__global__ __launch_bounds__(256) void rescore_kernel(const float* __restrict__ x,
                                                      const float* __restrict__ cb) {
    __shared__ float xs[8][DD];
    const int tid = threadIdx.x, w = tid >> 5, lane = tid & 31;
    const int n = blockIdx.x * 8 + w;
    const int b = n >> 10, hw = n & (HW - 1);
    const float* xp = x + (size_t)b * IMG + hw;
#pragma unroll
    for (int d = lane; d < DD; d += 32) xs[w][d] = xp[(size_t)d * HW];
    __syncwarp();

    const int cnt = g_ccnt[n];
    const float xn = g_xnorm[n];
    float bv = 3.4e38f;
    int   bi = 0x7FFFFFFF;

    if (cnt <= CAND_CAP) {
        for (int ci = lane; ci < cnt; ci += 32) {
            int k = g_cand[n * CAND_CAP + ci];
            const float* cp = cb + (size_t)k * DD;
            float m = 0.f;
#pragma unroll 8
            for (int d = 0; d < DD; ++d) m = fmaf(xs[w][d], cp[d], m);
            float dd = __fsub_rn(__fadd_rn(xn, g_cnorm[k]), 2.0f * m);
            if (dd < bv || (dd == bv && k < bi)) { bv = dd; bi = k; }
        }
    } else {   // overflow fallback: exact full scan
        for (int k = lane; k < KC; k += 32) {
            const float* cp = cb + (size_t)k * DD;
            float m = 0.f;
#pragma unroll 8
            for (int d = 0; d < DD; ++d) m = fmaf(xs[w][d], cp[d], m);
            float dd = __fsub_rn(__fadd_rn(xn, g_cnorm[k]), 2.0f * m);
            if (dd < bv || (dd == bv && k < bi)) { bv = dd; bi = k; }
        }
    }
#pragma unroll
    for (int off = 16; off; off >>= 1) {
        float ov = __shfl_xor_sync(0xffffffffu, bv, off);
        int   ob = __shfl_xor_sync(0xffffffffu, bi, off);
        if (ov < bv || (ov == bv && ob < bi)) { bv = ov; bi = ob; }
    }
    if (lane == 0) g_idx[n] = bi;
}

// ============================================================
// Kernel 6: gather quant, straight-through output, loss partial.
// ============================================================
__global__ __launch_bounds__(256) void epi_kernel(const float* __restrict__ x,
                                                  const float* __restrict__ cb,
                                                  float* __restrict__ out) {
    __shared__ int   sidx[64];
    __shared__ float swarp[8];
    const int tid  = threadIdx.x;
    const int tok0 = blockIdx.x * 64;
    const int bimg = tok0 >> 10;
    const int hw0  = tok0 & (HW - 1);

    if (tid < 64) sidx[tid] = g_idx[tok0 + tid];
    __syncthreads();

    const int m  = tid & 63;
    const int dh = tid >> 6;
    const size_t base = (size_t)bimg * IMG + hw0 + m;
    const long long crow = (long long)sidx[m] * DD;

    float lsum = 0.f;
#pragma unroll 8
    for (int d0 = 0; d0 < DD; d0 += 4) {
        int d = d0 + dh;
        float q  = cb[crow + d];
        size_t off = base + (size_t)d * HW;
        float xv = x[off];
        float t  = __fsub_rn(q, xv);
        out[off] = __fadd_rn(xv, t);
        lsum = fmaf(t, t, lsum);
    }
#pragma unroll
    for (int off = 16; off; off >>= 1) lsum += __shfl_xor_sync(0xffffffffu, lsum, off);
    if ((tid & 31) == 0) swarp[tid >> 5] = lsum;
    __syncthreads();
    if (tid == 0) {
        float s = 0.f;
        for (int wq = 0; wq < 8; ++wq) s += swarp[wq];
        g_partial[blockIdx.x] = s;
    }
    if (tid < 64) out[OUT_ENC + tok0 + tid] = (float)sidx[tid];
}

// ============================================================
// Kernel 7: finalize loss
// ============================================================
__global__ __launch_bounds__(256) void fin_kernel(float* __restrict__ out) {
    __shared__ float sw[8];
    int tid = threadIdx.x;
    float s = g_partial[tid];
#pragma unroll
    for (int off = 16; off; off >>= 1) s += __shfl_xor_sync(0xffffffffu, s, off);
    if ((tid & 31) == 0) sw[tid >> 5] = s;
    __syncthreads();
    if (tid == 0) {
        float tot = 0.f;
        for (int wq = 0; wq < 8; ++wq) tot += sw[wq];
        float mse = tot / 4194304.0f;
        out[OUT_LOSS] = __fadd_rn(mse, __fmul_rn(0.25f, mse));
    }
}

// ============================================================
extern "C" void kernel_launch(void* const* d_in, const int* in_sizes, int n_in,
                              void* d_out, int out_size) {
    const float* x  = (const float*)d_in[0];   // [16,256,32,32] fp32
    const float* cb = (const float*)d_in[1];   // [8192,256] fp32
    float* out = (float*)d_out;

    cudaFuncSetAttribute(gemm_kernel,
                         cudaFuncAttributeMaxDynamicSharedMemorySize, GEMM_SMEM);

    norms_kernel<<<96, 256>>>(x, cb);
    convert_kernel<<<3072, 256>>>(x, cb);
    gemm_kernel<<<4096, 512, GEMM_SMEM>>>();
    collect_kernel<<<1024, 256>>>();
    rescore_kernel<<<NTOK / 8, 256>>>(x, cb);
    epi_kernel<<<256, 256>>>(x, cb, out);
    fin_kernel<<<1, 256>>>(out);
}